// round 5
// baseline (speedup 1.0000x reference)
#include <cuda_runtime.h>
#include <math.h>

// SimplexLayer: out = gelu( sum_e softmax(h@Wr^T + br)[:,e] * (h @ We[e]^T) + bias )
// B=4, S=4096, D=1024, E=8.
// Strategy: fold routing weight into A, single NT-GEMM with K' = E*D = 8192.

#define Bq 4
#define Sq 4096
#define Dq 1024
#define Eq 8
#define MT (Bq * Sq)   // 16384 tokens

// Scratch for routing weights (no cudaMalloc allowed).
__device__ float g_rw[MT * Eq];

// ---------------------------------------------------------------------------
// Kernel 1: routing logits + softmax. One warp per token.
// ---------------------------------------------------------------------------
__global__ void route_kernel(const float* __restrict__ h,
                             const float* __restrict__ Wr,
                             const float* __restrict__ br) {
    int gw   = (blockIdx.x * blockDim.x + threadIdx.x) >> 5;
    int lane = threadIdx.x & 31;
    if (gw >= MT) return;

    const float* hrow = h + (size_t)gw * Dq;
    float acc[Eq];
#pragma unroll
    for (int e = 0; e < Eq; e++) acc[e] = 0.f;

    for (int d = lane; d < Dq; d += 32) {
        float hv = hrow[d];
#pragma unroll
        for (int e = 0; e < Eq; e++)
            acc[e] = fmaf(hv, Wr[e * Dq + d], acc[e]);
    }
#pragma unroll
    for (int e = 0; e < Eq; e++) {
#pragma unroll
        for (int o = 16; o > 0; o >>= 1)
            acc[e] += __shfl_xor_sync(0xffffffffu, acc[e], o);
    }
    if (lane == 0) {
        float mx = -1e30f;
#pragma unroll
        for (int e = 0; e < Eq; e++) { acc[e] += br[e]; mx = fmaxf(mx, acc[e]); }
        float s = 0.f;
#pragma unroll
        for (int e = 0; e < Eq; e++) { acc[e] = expf(acc[e] - mx); s += acc[e]; }
        float inv = 1.f / s;
#pragma unroll
        for (int e = 0; e < Eq; e++) g_rw[gw * Eq + e] = acc[e] * inv;
    }
}

// ---------------------------------------------------------------------------
// Kernel 2: fused GEMM + bias + exact GELU.
// C[t,f] = sum_e sum_d (rw[t,e]*h[t,d]) * We[e,f,d]   (NT GEMM, K' = 8192)
// Tile 128x128, BK=16, 256 threads, 8x8 micro-tile per thread.
// ---------------------------------------------------------------------------
#define BM 128
#define BN 128
#define BK 16
#define PAD 130   // 4*PAD % 32 == 8 -> transposed STS is bank-conflict-free

__global__ __launch_bounds__(256, 2)
void moe_gemm_gelu_kernel(const float* __restrict__ h,
                          const float* __restrict__ We,
                          const float* __restrict__ bias,
                          float* __restrict__ out) {
    __shared__ float As[BK][PAD];
    __shared__ float Bs[BK][PAD];
    __shared__ float rw_s[BM];

    const int tid = threadIdx.x;
    const int tx  = tid & 15;
    const int ty  = tid >> 4;
    const int m0  = blockIdx.y * BM;
    const int n0  = blockIdx.x * BN;

    const int lrow = tid >> 2;        // 0..63 (coalesced: 4 threads per row)
    const int lk4  = (tid & 3) * 4;   // float4 slot within 16-float K chunk

    float acc[8][8];
#pragma unroll
    for (int i = 0; i < 8; i++)
#pragma unroll
        for (int j = 0; j < 8; j++) acc[i][j] = 0.f;

    for (int e = 0; e < Eq; e++) {
        // Routing weights for this expert / this M-tile.
        // Safe: previous iteration ended on __syncthreads(), and rw_s reads
        // all happened before that barrier.
        if (tid < BM) rw_s[tid] = g_rw[(size_t)(m0 + tid) * Eq + e];
        __syncthreads();

        const float* Bbase = We + (size_t)e * Dq * Dq;

        for (int k0 = 0; k0 < Dq; k0 += BK) {
            // Load + transpose A tile, scaling by rw (folds expert weight in)
#pragma unroll
            for (int r = 0; r < 2; r++) {
                int row = lrow + r * 64;
                float4 v = *(const float4*)(h + (size_t)(m0 + row) * Dq + k0 + lk4);
                float s = rw_s[row];
                As[lk4 + 0][row] = v.x * s;
                As[lk4 + 1][row] = v.y * s;
                As[lk4 + 2][row] = v.z * s;
                As[lk4 + 3][row] = v.w * s;
            }
            // Load + transpose B tile (W_e rows, K-contiguous)
#pragma unroll
            for (int r = 0; r < 2; r++) {
                int row = lrow + r * 64;
                float4 v = *(const float4*)(Bbase + (size_t)(n0 + row) * Dq + k0 + lk4);
                Bs[lk4 + 0][row] = v.x;
                Bs[lk4 + 1][row] = v.y;
                Bs[lk4 + 2][row] = v.z;
                Bs[lk4 + 3][row] = v.w;
            }
            __syncthreads();

#pragma unroll
            for (int k = 0; k < BK; k++) {
                float a[8], b[8];
#pragma unroll
                for (int i = 0; i < 4; i++) {
                    a[i]     = As[k][ty * 4 + i];
                    a[i + 4] = As[k][ty * 4 + 64 + i];
                    b[i]     = Bs[k][tx * 4 + i];
                    b[i + 4] = Bs[k][tx * 4 + 64 + i];
                }
#pragma unroll
                for (int i = 0; i < 8; i++)
#pragma unroll
                    for (int j = 0; j < 8; j++)
                        acc[i][j] = fmaf(a[i], b[j], acc[i][j]);
            }
            __syncthreads();
        }
    }

    // Epilogue: bias + exact GELU (erf form, matching approximate=False)
#pragma unroll
    for (int i = 0; i < 8; i++) {
        int row = m0 + ty * 4 + (i < 4 ? i : 60 + i);
#pragma unroll
        for (int j = 0; j < 8; j++) {
            int col = n0 + tx * 4 + (j < 4 ? j : 60 + j);
            float v = acc[i][j] + bias[col];
            float g = 0.5f * v * (1.0f + erff(v * 0.7071067811865476f));
            out[(size_t)row * Dq + col] = g;
        }
    }
}

// ---------------------------------------------------------------------------
extern "C" void kernel_launch(void* const* d_in, const int* in_sizes, int n_in,
                              void* d_out, int out_size) {
    const float* h  = (const float*)d_in[0];   // [B,S,D]
    const float* Wr = (const float*)d_in[1];   // [E,D]
    const float* br = (const float*)d_in[2];   // [E]
    const float* We = (const float*)d_in[3];   // [E,D,D]
    const float* lb = (const float*)d_in[4];   // [D]
    float* out = (float*)d_out;                // [B,S,D]

    route_kernel<<<MT / 8, 256>>>(h, Wr, br);

    dim3 grid(Dq / BN, MT / BM);   // (8, 128)
    moe_gemm_gelu_kernel<<<grid, 256>>>(h, We, lb, out);
}

// round 10
// speedup vs baseline: 2.4378x; 2.4378x over previous
#include <cuda_runtime.h>
#include <cstdint>
#include <math.h>

// SimplexLayer: out = gelu( sum_e softmax(h@Wr^T+br)[:,e] * (h @ We[e]^T) + bias )
// B=4, S=4096, D=1024, E=8.  Single NT-GEMM, K' = E*D = 8192, rw folded into A.
// tcgen05 is blocked by the toolchain (PTX virtual target = compute_103, no 'a'),
// so the tensor path is mma.sync m16n8k8 tf32 with explicit rna rounding.

#define Dq 1024
#define Eq 8
#define MT 16384

__device__ float g_rw[MT * Eq];

// ---------------------------------------------------------------------------
// Kernel 1: routing logits + softmax. One warp per token.
// ---------------------------------------------------------------------------
__global__ void route_kernel(const float* __restrict__ h,
                             const float* __restrict__ Wr,
                             const float* __restrict__ br) {
    int gw   = (blockIdx.x * blockDim.x + threadIdx.x) >> 5;
    int lane = threadIdx.x & 31;
    if (gw >= MT) return;

    const float* hrow = h + (size_t)gw * Dq;
    float acc[Eq];
#pragma unroll
    for (int e = 0; e < Eq; e++) acc[e] = 0.f;

    for (int d = lane; d < Dq; d += 32) {
        float hv = hrow[d];
#pragma unroll
        for (int e = 0; e < Eq; e++)
            acc[e] = fmaf(hv, Wr[e * Dq + d], acc[e]);
    }
#pragma unroll
    for (int e = 0; e < Eq; e++) {
#pragma unroll
        for (int o = 16; o > 0; o >>= 1)
            acc[e] += __shfl_xor_sync(0xffffffffu, acc[e], o);
    }
    if (lane == 0) {
        float mx = -1e30f;
#pragma unroll
        for (int e = 0; e < Eq; e++) { acc[e] += br[e]; mx = fmaxf(mx, acc[e]); }
        float s = 0.f;
#pragma unroll
        for (int e = 0; e < Eq; e++) { acc[e] = expf(acc[e] - mx); s += acc[e]; }
        float inv = 1.f / s;
#pragma unroll
        for (int e = 0; e < Eq; e++) g_rw[gw * Eq + e] = acc[e] * inv;
    }
}

// ---------------------------------------------------------------------------
// Kernel 2: tf32 mma.sync GEMM, CTA tile 128x256, warp tile 64x64, BK=16.
// ---------------------------------------------------------------------------
#define SA 20                          // padded smem row stride (floats); 20 % 32 == 4*? ->
                                       // 20*g mod 32 = {0,20,8,28,16,4,24,12}: frag LDS conflict-free
#define A_OFF 1024                     // floats: rw_sm occupies [0,1024)
#define B_OFF (A_OFF + 2 * 128 * SA)   // A: 2 buffers of 128 rows
#define SMEM_WORDS (B_OFF + 2 * 256 * SA)
#define SMEM_BYTES (SMEM_WORDS * 4)    // 65536 B

__device__ __forceinline__ uint32_t tf32r(float x) {   // round-to-nearest fp32 -> tf32
    uint32_t o;
    asm("cvt.rna.tf32.f32 %0, %1;" : "=r"(o) : "f"(x));
    return o;
}

__device__ __forceinline__ void mma8(float* d, const uint32_t* a, const uint32_t* b) {
    asm volatile(
        "mma.sync.aligned.m16n8k8.row.col.f32.tf32.tf32.f32 "
        "{%0,%1,%2,%3}, {%4,%5,%6,%7}, {%8,%9}, {%0,%1,%2,%3};"
        : "+f"(d[0]), "+f"(d[1]), "+f"(d[2]), "+f"(d[3])
        : "r"(a[0]), "r"(a[1]), "r"(a[2]), "r"(a[3]), "r"(b[0]), "r"(b[1]));
}

__device__ __forceinline__ float gelu_exact(float v) {
    return 0.5f * v * (1.0f + erff(v * 0.7071067811865476f));
}

__global__ __launch_bounds__(256, 1)
void simplex_mma_tf32(const float* __restrict__ h,
                      const float* __restrict__ We,
                      const float* __restrict__ bias,
                      float* __restrict__ out) {
    extern __shared__ uint32_t sm[];
    float*    rw_sm = (float*)sm;         // [128][8]
    uint32_t* As    = sm + A_OFF;         // [2][128][SA]
    uint32_t* Bs    = sm + B_OFF;         // [2][256][SA]

    const int tid  = threadIdx.x;
    const int wid  = tid >> 5;
    const int lane = tid & 31;
    const int g    = lane >> 2;           // 0..7
    const int tg   = lane & 3;            // 0..3
    const int m0   = blockIdx.y * 128;
    const int n0   = blockIdx.x * 256;
    const int wm   = (wid & 1) * 64;      // warp m-offset (2 warps in m)
    const int wn   = (wid >> 1) * 64;     // warp n-offset (4 warps in n)

    // routing weights for this M-tile: 128 tokens x 8 experts
    ((float4*)rw_sm)[tid] = ((const float4*)(g_rw + (size_t)m0 * Eq))[tid];
    __syncthreads();

    float acc[4][8][4];
#pragma unroll
    for (int mi = 0; mi < 4; mi++)
#pragma unroll
        for (int ni = 0; ni < 8; ni++)
#pragma unroll
            for (int q = 0; q < 4; q++) acc[mi][ni][q] = 0.f;

    const int lr = tid >> 2;              // 0..63  (global-load row base)
    const int lc = (tid & 3) * 4;         // 0,4,8,12

    float4 ra[2], rb[4];
    int e_pf = 0;                         // expert of the prefetched tile

    // ---- prefetch tile `it` into registers ----
#define LDG_TILE(it) do {                                                        \
        int _e  = (it) >> 6;                                                     \
        int _k0 = ((it) & 63) << 4;                                              \
        e_pf = _e;                                                               \
        const float* _hp = h + (size_t)(m0 + lr) * Dq + _k0 + lc;                \
        ra[0] = *(const float4*)_hp;                                             \
        ra[1] = *(const float4*)(_hp + 64 * Dq);                                 \
        const float* _bp = We + (size_t)_e * Dq * Dq                             \
                              + (size_t)(n0 + lr) * Dq + _k0 + lc;               \
        rb[0] = *(const float4*)_bp;                                             \
        rb[1] = *(const float4*)(_bp + 64 * Dq);                                 \
        rb[2] = *(const float4*)(_bp + 128 * Dq);                                \
        rb[3] = *(const float4*)(_bp + 192 * Dq);                                \
    } while (0)

    // ---- scale (A only) + rna-round + store to smem buffer ----
#define STS_TILE(buf) do {                                                       \
        uint32_t* _Ad = As + (buf) * 128 * SA;                                   \
        _Pragma("unroll")                                                        \
        for (int _p = 0; _p < 2; _p++) {                                         \
            int _row = lr + _p * 64;                                             \
            float _s = rw_sm[_row * Eq + e_pf];                                  \
            float4 _v = ra[_p];                                                  \
            uint4 _w = { tf32r(_v.x * _s), tf32r(_v.y * _s),                     \
                         tf32r(_v.z * _s), tf32r(_v.w * _s) };                   \
            *(uint4*)(_Ad + _row * SA + lc) = _w;                                \
        }                                                                        \
        uint32_t* _Bd = Bs + (buf) * 256 * SA;                                   \
        _Pragma("unroll")                                                        \
        for (int _p = 0; _p < 4; _p++) {                                         \
            int _row = lr + _p * 64;                                             \
            float4 _v = rb[_p];                                                  \
            uint4 _w = { tf32r(_v.x), tf32r(_v.y), tf32r(_v.z), tf32r(_v.w) };   \
            *(uint4*)(_Bd + _row * SA + lc) = _w;                                \
        }                                                                        \
    } while (0)

    LDG_TILE(0);
    STS_TILE(0);
    __syncthreads();

    const int NIT = Eq * (Dq / 16);       // 512 mainloop iterations
    for (int it = 0; it < NIT; ++it) {
        const int cur = it & 1;
        if (it + 1 < NIT) LDG_TILE(it + 1);

        const uint32_t* Ab = As + cur * 128 * SA;
        const uint32_t* Bb = Bs + cur * 256 * SA;
#pragma unroll
        for (int ks = 0; ks < 2; ks++) {
            const int kc = ks * 8 + tg;
            uint32_t af[4][4], bf[8][2];
#pragma unroll
            for (int mi = 0; mi < 4; mi++) {
                const uint32_t* p = Ab + (wm + mi * 16 + g) * SA + kc;
                af[mi][0] = p[0];            // (g,      tg)
                af[mi][1] = p[8 * SA];       // (g + 8,  tg)
                af[mi][2] = p[4];            // (g,      tg+4)
                af[mi][3] = p[8 * SA + 4];   // (g + 8,  tg+4)
            }
#pragma unroll
            for (int ni = 0; ni < 8; ni++) {
                const uint32_t* p = Bb + (wn + ni * 8 + g) * SA + kc;
                bf[ni][0] = p[0];            // (k=tg,   n=g)
                bf[ni][1] = p[4];            // (k=tg+4, n=g)
            }
#pragma unroll
            for (int mi = 0; mi < 4; mi++)
#pragma unroll
                for (int ni = 0; ni < 8; ni++)
                    mma8(acc[mi][ni], af[mi], bf[ni]);
        }

        if (it + 1 < NIT) STS_TILE(cur ^ 1);
        __syncthreads();
    }

    // ---- epilogue: bias + exact erf GELU ----
#pragma unroll
    for (int mi = 0; mi < 4; mi++) {
        const int r0 = m0 + wm + mi * 16 + g;
#pragma unroll
        for (int ni = 0; ni < 8; ni++) {
            const int c = n0 + wn + ni * 8 + tg * 2;
            const float b0v = bias[c], b1v = bias[c + 1];
            float2 o;
            o.x = gelu_exact(acc[mi][ni][0] + b0v);
            o.y = gelu_exact(acc[mi][ni][1] + b1v);
            *(float2*)(out + (size_t)r0 * Dq + c) = o;
            o.x = gelu_exact(acc[mi][ni][2] + b0v);
            o.y = gelu_exact(acc[mi][ni][3] + b1v);
            *(float2*)(out + (size_t)(r0 + 8) * Dq + c) = o;
        }
    }
}

// ---------------------------------------------------------------------------
extern "C" void kernel_launch(void* const* d_in, const int* in_sizes, int n_in,
                              void* d_out, int out_size) {
    const float* h  = (const float*)d_in[0];   // [B,S,D]
    const float* Wr = (const float*)d_in[1];   // [E,D]
    const float* br = (const float*)d_in[2];   // [E]
    const float* We = (const float*)d_in[3];   // [E,D,D]
    const float* lb = (const float*)d_in[4];   // [D]
    float* out = (float*)d_out;                // [B,S,D]

    cudaFuncSetAttribute(simplex_mma_tf32,
                         cudaFuncAttributeMaxDynamicSharedMemorySize, SMEM_BYTES);

    route_kernel<<<MT / 8, 256>>>(h, Wr, br);

    dim3 grid(Dq / 256, MT / 128);             // (4, 128) = 512 CTAs
    simplex_mma_tf32<<<grid, 256, SMEM_BYTES>>>(h, We, lb, out);
}